// round 17
// baseline (speedup 1.0000x reference)
#include <cuda_runtime.h>

#define SEQ    2048
#define DIM    4096
#define BATCH  4
#define PAD_ID 50256
#define NROWS  (2 * BATCH * SEQ)     // 16384
#define TPB    256                   // 8 warps/block
#define NPAIR  (BATCH * SEQ)         // 8192 (b,s) pairs, one per warp
#define NBLK   (NPAIR / 8)           // 1024 blocks

__device__ unsigned int g_counter = 0;     // block-arrival tickets
__device__ unsigned int g_ready   = 0;     // pre-pass done count (0..4)
__device__ int          g_div[BATCH];
__device__ int          g_end[BATCH];
__device__ float        g_sc[BATCH];       // masked sum chosen
__device__ float        g_sr[BATCH];       // masked sum rejected
__device__ float        g_sl[BATCH];       // masked sum loss terms

// ---------------------------------------------------------------------------
// Row-paired fused kernel: warp p computes BOTH dot(hs[b,s]) and dot(hs[b+4,s])
// sharing one w load; loss/mean terms accumulated inline via L2 atomics.
// Pre-pass (blocks 0-3) publishes div/end + zeroes accumulators; finisher
// block (last ticket) writes the 13 scalar outputs.
// ---------------------------------------------------------------------------
__global__ void __launch_bounds__(TPB, 1)
reward_fused_kernel(const float* __restrict__ hs,
                    const float* __restrict__ w,
                    const int*   __restrict__ ids,
                    float*       __restrict__ out) {
    float* rewards = out + 1;                       // [2B*S]
    const int tid  = threadIdx.x;
    const int lane = tid & 31;
    const int warp = tid >> 5;

    __shared__ int sh_min[3];
    __shared__ unsigned int sh_ticket;

    // ---- pre-pass: blocks 0..3 compute div/end, zero accumulators ----
    if (blockIdx.x < BATCH) {
        const int pb = blockIdx.x;
        if (tid < 3) sh_min[tid] = SEQ;
        __syncthreads();
        const int4* cid4 = reinterpret_cast<const int4*>(ids + (size_t)pb * SEQ);
        const int4* rid4 = reinterpret_cast<const int4*>(ids + (size_t)(pb + BATCH) * SEQ);
        int dloc = SEQ, cloc = SEQ, rloc = SEQ;
        for (int i = tid; i < SEQ / 4; i += TPB) {
            int4 c = cid4[i];
            int4 r = rid4[i];
            int s = i * 4;
            if (c.x != r.x)    dloc = min(dloc, s + 0);
            if (c.y != r.y)    dloc = min(dloc, s + 1);
            if (c.z != r.z)    dloc = min(dloc, s + 2);
            if (c.w != r.w)    dloc = min(dloc, s + 3);
            if (c.x == PAD_ID) cloc = min(cloc, s + 0);
            if (c.y == PAD_ID) cloc = min(cloc, s + 1);
            if (c.z == PAD_ID) cloc = min(cloc, s + 2);
            if (c.w == PAD_ID) cloc = min(cloc, s + 3);
            if (r.x == PAD_ID) rloc = min(rloc, s + 0);
            if (r.y == PAD_ID) rloc = min(rloc, s + 1);
            if (r.z == PAD_ID) rloc = min(rloc, s + 2);
            if (r.w == PAD_ID) rloc = min(rloc, s + 3);
        }
        atomicMin(&sh_min[0], dloc);
        atomicMin(&sh_min[1], cloc);
        atomicMin(&sh_min[2], rloc);
        __syncthreads();
        if (tid == 0) {
            g_div[pb] = sh_min[0];
            g_end[pb] = max(sh_min[1], sh_min[2]);
            g_sc[pb] = 0.0f; g_sr[pb] = 0.0f; g_sl[pb] = 0.0f;
            __threadfence();
            atomicAdd(&g_ready, 1u);                // publish
        }
        __syncthreads();
    }

    // ---- paired matvec: warp p -> (b, s); dots for chosen AND rejected ----
    {
        const int p = blockIdx.x * (TPB / 32) + warp;   // 0..NPAIR-1
        const int b = p >> 11;                          // p / SEQ
        const int s = p & (SEQ - 1);                    // p % SEQ

        const float4* rc = reinterpret_cast<const float4*>(hs + (size_t)(b * SEQ + s) * DIM);
        const float4* rj = reinterpret_cast<const float4*>(hs + (size_t)((b + BATCH) * SEQ + s) * DIM);
        const float4* w4 = reinterpret_cast<const float4*>(w);

        float ac = 0.0f, ar = 0.0f;
        #pragma unroll 4
        for (int i = lane; i < DIM / 4; i += 32) {
            float4 wv = __ldg(&w4[i]);
            float4 a  = __ldg(&rc[i]);
            float4 bb = __ldg(&rj[i]);
            ac = fmaf(a.x,  wv.x, ac);
            ac = fmaf(a.y,  wv.y, ac);
            ac = fmaf(a.z,  wv.z, ac);
            ac = fmaf(a.w,  wv.w, ac);
            ar = fmaf(bb.x, wv.x, ar);
            ar = fmaf(bb.y, wv.y, ar);
            ar = fmaf(bb.z, wv.z, ar);
            ar = fmaf(bb.w, wv.w, ar);
        }
        #pragma unroll
        for (int off = 16; off > 0; off >>= 1) {
            ac += __shfl_xor_sync(0xffffffffu, ac, off);
            ar += __shfl_xor_sync(0xffffffffu, ar, off);
        }

        if (lane == 0) {
            rewards[b * SEQ + s]           = ac;
            rewards[(b + BATCH) * SEQ + s] = ar;

            // wait for div/end (pre-pass finishes long before first dot does)
            volatile unsigned int* vr = &g_ready;
            while (*vr < (unsigned)BATCH) { /* spin */ }
            __threadfence();
            const int dv = g_div[b];
            const int en = g_end[b];

            if (s >= dv && s < en) {
                float x = ac - ar;
                float lt = fmaxf(-x, 0.0f) + log1pf(expf(-fabsf(x)));
                atomicAdd(&g_sc[b], ac);
                atomicAdd(&g_sr[b], ar);
                atomicAdd(&g_sl[b], lt);
            }
            if (s == max(en - 1, 0)) {
                float* out_ce = out + 1 + NROWS + 2 * BATCH;
                float* out_re = out_ce + BATCH;
                out_ce[b] = ac;
                out_re[b] = ar;
            }
            __threadfence();                        // publish adds before ticket
        }
    }

    // ---- ticket; last block finalizes scalars ----
    __syncthreads();
    if (tid == 0) {
        __threadfence();
        sh_ticket = atomicAdd(&g_counter, 1u);
    }
    __syncthreads();
    if (sh_ticket != (unsigned)NBLK - 1u) return;

    if (tid == 0) {
        volatile unsigned int* vc = &g_counter;
        while (*vc < (unsigned)NBLK) { /* spin */ }
        __threadfence();

        float* out_cm = out + 1 + NROWS;            // chosen_mean[4]
        float* out_rm = out_cm + BATCH;             // rejected_mean[4]
        float loss = 0.0f;
        #pragma unroll
        for (int b = 0; b < BATCH; b++) {
            int window = g_end[b] - g_div[b];
            float fcnt = fmaxf((float)window, 1.0f);
            out_cm[b] = g_sc[b] / fcnt;
            out_rm[b] = g_sr[b] / fcnt;
            loss += g_sl[b] / fcnt;
        }
        out[0] = loss * (1.0f / (float)BATCH);

        // reset for next graph replay
        atomicExch(&g_ready, 0u);
        atomicExch(&g_counter, 0u);
    }
}

// ---------------------------------------------------------------------------
extern "C" void kernel_launch(void* const* d_in, const int* in_sizes, int n_in,
                              void* d_out, int out_size) {
    const float* hs  = (const float*)d_in[0];       // (2B, S, D) fp32
    const float* w   = (const float*)d_in[1];       // (D,) fp32
    const int*   ids = (const int*)d_in[2];         // (2B, S) int32

    reward_fused_kernel<<<NBLK, TPB>>>(hs, w, ids, (float*)d_out);
}